// round 9
// baseline (speedup 1.0000x reference)
#include <cuda_runtime.h>

#define H 128
#define NMAX 50000
#define TEK 64          // edges per block (edge kernel)
#define TNP 4           // node pairs per group
#define GN (2*TNP)
#define TN (2*GN)

// Scratch (no dynamic allocation allowed)
__device__ float g_agg[NMAX * H];
__device__ float g_dx[NMAX * 3];
__device__ float g_cnt[NMAX];
__device__ float g_P[NMAX * H];        // h @ We1[0:128]
__device__ float g_Q[NMAX * H];        // h @ We1[128:256]
__device__ float g_W2e[16 * 16 * 32 * 2];  // We2 fragment-swizzled tf32
__device__ float g_W2c[16 * 16 * 32 * 2];  // Wc1 fragment-swizzled tf32

typedef unsigned long long u64;

__device__ __forceinline__ void ffma2(u64 &acc, u64 a, u64 b) {
    asm("fma.rn.f32x2 %0, %1, %2, %0;" : "+l"(acc) : "l"(a), "l"(b));
}
__device__ __forceinline__ u64 pack2(float v) {
    u64 r; unsigned u = __float_as_uint(v);
    asm("mov.b64 %0, {%1, %1};" : "=l"(r) : "r"(u));
    return r;
}
__device__ __forceinline__ float2 unpack2(u64 v) {
    unsigned lo, hi;
    asm("mov.b64 {%0, %1}, %2;" : "=r"(lo), "=r"(hi) : "l"(v));
    return make_float2(__uint_as_float(lo), __uint_as_float(hi));
}
__device__ __forceinline__ float silu(float v) {
    return v / (1.0f + __expf(-v));
}
__device__ __forceinline__ float2 silu2(u64 v) {
    float2 f = unpack2(v);
    return make_float2(silu(f.x), silu(f.y));
}
__device__ __forceinline__ unsigned tf32u(float f) {
    unsigned r; asm("cvt.rna.tf32.f32 %0, %1;" : "=r"(r) : "f"(f));
    return r;
}
__device__ __forceinline__ float tf32f(float f) {
    return __uint_as_float(tf32u(f));
}
__device__ __forceinline__ void mma_tf32(float c[4],
    unsigned a0, unsigned a1, unsigned a2, unsigned a3,
    unsigned b0, unsigned b1)
{
    asm("mma.sync.aligned.m16n8k8.row.col.f32.tf32.tf32.f32 "
        "{%0,%1,%2,%3},{%4,%5,%6,%7},{%8,%9},{%0,%1,%2,%3};"
        : "+f"(c[0]), "+f"(c[1]), "+f"(c[2]), "+f"(c[3])
        : "r"(a0), "r"(a1), "r"(a2), "r"(a3), "r"(b0), "r"(b1));
}
__device__ __forceinline__ void ldsm4(unsigned &r0, unsigned &r1,
                                      unsigned &r2, unsigned &r3,
                                      unsigned addr)
{
    asm volatile("ldmatrix.sync.aligned.m8n8.x4.shared.b16 {%0,%1,%2,%3}, [%4];"
        : "=r"(r0), "=r"(r1), "=r"(r2), "=r"(r3) : "r"(addr));
}

__global__ void zero_kernel(int n) {
    int total = n * H + n * 3 + n;
    for (int i = blockIdx.x * blockDim.x + threadIdx.x; i < total;
         i += gridDim.x * blockDim.x) {
        if (i < n * H) g_agg[i] = 0.0f;
        else if (i < n * H + n * 3) g_dx[i - n * H] = 0.0f;
        else g_cnt[i - n * H - n * 3] = 0.0f;
    }
}

// Fragment-swizzle We2 and Wc1 into tf32 B-frag order:
// g_W2*[((tp*16+s)*32+lane)*2 + r] = tf32(W[8s + tg + 4r][8tp + g])
__global__ void prep_kernel(const float* __restrict__ We2,
                            const float* __restrict__ Wc1)
{
    int i = blockIdx.x * blockDim.x + threadIdx.x;
    if (i >= 16 * 16 * 32 * 2) return;
    int r    = i & 1;
    int lane = (i >> 1) & 31;
    int s    = (i >> 6) & 15;
    int tp   = i >> 10;
    int g = lane >> 2, tg = lane & 3;
    int k = 8 * s + tg + 4 * r;
    int n = 8 * tp + g;
    g_W2e[i] = tf32f(We2[k * H + n]);
    g_W2c[i] = tf32f(Wc1[k * H + n]);
}

// ---------------------------------------------------------------------------
// PQ precompute: P = h @ We1[0:128,:], Q = h @ We1[128:256,:]  (f32x2 path)
// ---------------------------------------------------------------------------
__global__ __launch_bounds__(128) void pq_kernel(
    const float* __restrict__ h, const float* __restrict__ We1, int n)
{
    __shared__ float2 s_h[2][TNP][H];
    const int j = threadIdx.x;
    const int g = j >> 6;
    const int t = j & 63;
    const int c0 = t, c1 = t + 64;
    const int n0 = blockIdx.x * TN + g * GN;

    #pragma unroll
    for (int p = 0; p < TNP; p++) {
        int na = n0 + 2 * p, nb = na + 1;
        float a0 = 0.f, a1 = 0.f, b0 = 0.f, b1 = 0.f;
        if (na < n) { a0 = h[(long)na * H + c0]; a1 = h[(long)na * H + c1]; }
        if (nb < n) { b0 = h[(long)nb * H + c0]; b1 = h[(long)nb * H + c1]; }
        s_h[g][p][c0] = make_float2(a0, b0);
        s_h[g][p][c1] = make_float2(a1, b1);
    }
    __syncthreads();

    u64 accP0[TNP], accP1[TNP], accQ0[TNP], accQ1[TNP];
    #pragma unroll
    for (int p = 0; p < TNP; p++) {
        accP0[p] = 0; accP1[p] = 0; accQ0[p] = 0; accQ1[p] = 0;
    }

    #pragma unroll 2
    for (int kk = 0; kk < 32; kk++) {
        int k = kk * 4;
        u64 pa0 = pack2(We1[(k + 0) * H + c0]);
        u64 pa1 = pack2(We1[(k + 1) * H + c0]);
        u64 pa2 = pack2(We1[(k + 2) * H + c0]);
        u64 pa3 = pack2(We1[(k + 3) * H + c0]);
        u64 pb0 = pack2(We1[(k + 0) * H + c1]);
        u64 pb1 = pack2(We1[(k + 1) * H + c1]);
        u64 pb2 = pack2(We1[(k + 2) * H + c1]);
        u64 pb3 = pack2(We1[(k + 3) * H + c1]);
        u64 qa0 = pack2(We1[(128 + k + 0) * H + c0]);
        u64 qa1 = pack2(We1[(128 + k + 1) * H + c0]);
        u64 qa2 = pack2(We1[(128 + k + 2) * H + c0]);
        u64 qa3 = pack2(We1[(128 + k + 3) * H + c0]);
        u64 qb0 = pack2(We1[(128 + k + 0) * H + c1]);
        u64 qb1 = pack2(We1[(128 + k + 1) * H + c1]);
        u64 qb2 = pack2(We1[(128 + k + 2) * H + c1]);
        u64 qb3 = pack2(We1[(128 + k + 3) * H + c1]);
        #pragma unroll
        for (int p = 0; p < TNP; p++) {
            ulonglong2 A0 = *(const ulonglong2*)&s_h[g][p][k];
            ulonglong2 A1 = *(const ulonglong2*)&s_h[g][p][k + 2];
            ffma2(accP0[p], A0.x, pa0); ffma2(accP1[p], A0.x, pb0);
            ffma2(accQ0[p], A0.x, qa0); ffma2(accQ1[p], A0.x, qb0);
            ffma2(accP0[p], A0.y, pa1); ffma2(accP1[p], A0.y, pb1);
            ffma2(accQ0[p], A0.y, qa1); ffma2(accQ1[p], A0.y, qb1);
            ffma2(accP0[p], A1.x, pa2); ffma2(accP1[p], A1.x, pb2);
            ffma2(accQ0[p], A1.x, qa2); ffma2(accQ1[p], A1.x, qb2);
            ffma2(accP0[p], A1.y, pa3); ffma2(accP1[p], A1.y, pb3);
            ffma2(accQ0[p], A1.y, qa3); ffma2(accQ1[p], A1.y, qb3);
        }
    }

    #pragma unroll
    for (int p = 0; p < TNP; p++) {
        int na = n0 + 2 * p, nb = na + 1;
        float2 vP0 = unpack2(accP0[p]), vP1 = unpack2(accP1[p]);
        float2 vQ0 = unpack2(accQ0[p]), vQ1 = unpack2(accQ1[p]);
        if (na < n) {
            g_P[(long)na * H + c0] = vP0.x; g_P[(long)na * H + c1] = vP1.x;
            g_Q[(long)na * H + c0] = vQ0.x; g_Q[(long)na * H + c1] = vQ1.x;
        }
        if (nb < n) {
            g_P[(long)nb * H + c0] = vP0.y; g_P[(long)nb * H + c1] = vP1.y;
            g_Q[(long)nb * H + c0] = vQ0.y; g_Q[(long)nb * H + c1] = vQ1.y;
        }
    }
}

// ---------------------------------------------------------------------------
// Edge kernel: 64 edges/block; warps split N (32 cols each), 4 m16 tiles
// per warp. A via ldmatrix; single tf32 smem buffer recycled f1 -> f2.
// ---------------------------------------------------------------------------
__global__ __launch_bounds__(128) void edge_kernel(
    const float* __restrict__ x, const int* __restrict__ ei, int E,
    const float* __restrict__ We1, const float* __restrict__ be1,
    const float* __restrict__ be2, const float* __restrict__ bc1,
    const float* __restrict__ Wc2, const float* __restrict__ bc2)
{
    __shared__ float s_tf[TEK][132];
    __shared__ float s_rel[TEK][3];
    __shared__ float s_d2[TEK];
    __shared__ int   s_row[TEK], s_col[TEK];
    __shared__ float s_gp[4][TEK];
    __shared__ float s_gate[TEK];

    const int j = threadIdx.x;
    const int w = j >> 5, lane = j & 31;
    const int g = lane >> 2, tg = lane & 3;
    const long e0 = (long)blockIdx.x * TEK;

    // ldmatrix per-lane source addresses, one per m16 tile
    const int rowA = lane & 15;
    const int colA = (lane & 16) ? 4 : 0;
    unsigned baseA[4];
    #pragma unroll
    for (int mt = 0; mt < 4; mt++)
        baseA[mt] = (unsigned)__cvta_generic_to_shared(&s_tf[16 * mt + rowA][colA]);

    // Phase 0: per-edge scalars (64 edges, 2 per thread-half)
    if (j < TEK) {
        long e = e0 + j;
        int r = -1, c = 0;
        float rx = 0.f, ry = 0.f, rz = 0.f, d2 = 0.f;
        if (e < E) {
            r = ei[e]; c = ei[E + e];
            rx = x[r * 3 + 0] - x[c * 3 + 0];
            ry = x[r * 3 + 1] - x[c * 3 + 1];
            rz = x[r * 3 + 2] - x[c * 3 + 2];
            d2 = rx * rx + ry * ry + rz * rz;
        }
        s_row[j] = r; s_col[j] = c; s_d2[j] = d2;
        s_rel[j][0] = rx; s_rel[j][1] = ry; s_rel[j][2] = rz;
    }
    __syncthreads();

    // Phase 1: layer-1 elementwise (thread j = column j), stored tf32
    {
        float wl = We1[256 * H + j];
        float b  = be1[j];
        #pragma unroll 4
        for (int e = 0; e < TEK; e++) {
            int r = s_row[e], c = s_col[e];
            float v = 0.f;
            if (r >= 0)
                v = silu(g_P[(long)r * H + j] + g_Q[(long)c * H + j]
                         + s_d2[e] * wl + b);
            s_tf[e][j] = tf32f(v);
        }
    }
    __syncthreads();

    float cc[4][4][4];   // [t-tile][m-tile][frag]

    // ---- GEMM1: f2 = silu(f1 @ We2 + be2) ----
    #pragma unroll
    for (int t = 0; t < 4; t++)
        #pragma unroll
        for (int mt = 0; mt < 4; mt++)
            #pragma unroll
            for (int q = 0; q < 4; q++) cc[t][mt][q] = 0.f;

    #pragma unroll 2
    for (int s = 0; s < 16; s++) {
        unsigned a[4][4];
        #pragma unroll
        for (int mt = 0; mt < 4; mt++)
            ldsm4(a[mt][0], a[mt][1], a[mt][2], a[mt][3], baseA[mt] + 32u * s);
        #pragma unroll
        for (int t = 0; t < 4; t++) {
            float2 bv = *(const float2*)&g_W2e[(((4 * w + t) * 16 + s) * 32 + lane) * 2];
            unsigned b0 = __float_as_uint(bv.x), b1 = __float_as_uint(bv.y);
            #pragma unroll
            for (int mt = 0; mt < 4; mt++)
                mma_tf32(cc[t][mt], a[mt][0], a[mt][1], a[mt][2], a[mt][3], b0, b1);
        }
    }
    __syncthreads();   // all warps done reading s_tf (f1)

    // epilogue: silu + bias -> tf32 into s_tf (GEMM2 A operand AND scatter src)
    #pragma unroll
    for (int t = 0; t < 4; t++) {
        int col = 32 * w + 8 * t + 2 * tg;
        float b0 = be2[col], b1 = be2[col + 1];
        #pragma unroll
        for (int mt = 0; mt < 4; mt++) {
            int r0 = 16 * mt + g, r1 = r0 + 8;
            s_tf[r0][col]     = tf32f(silu(cc[t][mt][0] + b0));
            s_tf[r0][col + 1] = tf32f(silu(cc[t][mt][1] + b1));
            s_tf[r1][col]     = tf32f(silu(cc[t][mt][2] + b0));
            s_tf[r1][col + 1] = tf32f(silu(cc[t][mt][3] + b1));
        }
    }
    __syncthreads();

    // agg scatter (coalesced: thread j = column j), tf32-rounded f2
    #pragma unroll 4
    for (int e = 0; e < TEK; e++) {
        int r = s_row[e];
        if (r >= 0) atomicAdd(&g_agg[(long)r * H + j], s_tf[e][j]);
    }

    // ---- GEMM2: gate hidden = silu(f2 @ Wc1 + bc1), consumed in registers ----
    #pragma unroll
    for (int t = 0; t < 4; t++)
        #pragma unroll
        for (int mt = 0; mt < 4; mt++)
            #pragma unroll
            for (int q = 0; q < 4; q++) cc[t][mt][q] = 0.f;

    #pragma unroll 2
    for (int s = 0; s < 16; s++) {
        unsigned a[4][4];
        #pragma unroll
        for (int mt = 0; mt < 4; mt++)
            ldsm4(a[mt][0], a[mt][1], a[mt][2], a[mt][3], baseA[mt] + 32u * s);
        #pragma unroll
        for (int t = 0; t < 4; t++) {
            float2 bv = *(const float2*)&g_W2c[(((4 * w + t) * 16 + s) * 32 + lane) * 2];
            unsigned b0 = __float_as_uint(bv.x), b1 = __float_as_uint(bv.y);
            #pragma unroll
            for (int mt = 0; mt < 4; mt++)
                mma_tf32(cc[t][mt], a[mt][0], a[mt][1], a[mt][2], a[mt][3], b0, b1);
        }
    }

    // gate partial dot with Wc2; thread covers rows 16mt+g, 16mt+8+g
    {
        float p0[4], p1[4];
        #pragma unroll
        for (int mt = 0; mt < 4; mt++) { p0[mt] = 0.f; p1[mt] = 0.f; }
        #pragma unroll
        for (int t = 0; t < 4; t++) {
            int col = 32 * w + 8 * t + 2 * tg;
            float w0 = Wc2[col], w1 = Wc2[col + 1];
            float b0 = bc1[col], b1 = bc1[col + 1];
            #pragma unroll
            for (int mt = 0; mt < 4; mt++) {
                p0[mt] += silu(cc[t][mt][0] + b0) * w0 + silu(cc[t][mt][1] + b1) * w1;
                p1[mt] += silu(cc[t][mt][2] + b0) * w0 + silu(cc[t][mt][3] + b1) * w1;
            }
        }
        #pragma unroll
        for (int mt = 0; mt < 4; mt++) {
            p0[mt] += __shfl_xor_sync(0xffffffffu, p0[mt], 1);
            p0[mt] += __shfl_xor_sync(0xffffffffu, p0[mt], 2);
            p1[mt] += __shfl_xor_sync(0xffffffffu, p1[mt], 1);
            p1[mt] += __shfl_xor_sync(0xffffffffu, p1[mt], 2);
        }
        if (tg == 0) {
            #pragma unroll
            for (int mt = 0; mt < 4; mt++) {
                s_gp[w][16 * mt + g]     = p0[mt];
                s_gp[w][16 * mt + 8 + g] = p1[mt];
            }
        }
    }
    __syncthreads();

    if (j < TEK)
        s_gate[j] = s_gp[0][j] + s_gp[1][j] + s_gp[2][j] + s_gp[3][j] + bc2[0];
    __syncthreads();

    // dx/cnt scatter: 64 edges x 4 slots = 256 -> 2 rounds of 128 threads
    #pragma unroll
    for (int q = 0; q < 2; q++) {
        int idx = j + 128 * q;
        int e = idx >> 2, c = idx & 3;
        int r = s_row[e];
        if (r >= 0) {
            if (c < 3) atomicAdd(&g_dx[r * 3 + c], s_rel[e][c] * s_gate[e]);
            else       atomicAdd(&g_cnt[r], 1.0f);
        }
    }
}

// ---------------------------------------------------------------------------
// Node kernel (unchanged)
// ---------------------------------------------------------------------------
__global__ __launch_bounds__(128) void node_kernel(
    const float* __restrict__ x, const float* __restrict__ h, int n,
    const float* __restrict__ Wn1, const float* __restrict__ bn1,
    const float* __restrict__ Wn2, const float* __restrict__ bn2,
    const float* __restrict__ gamma, const float* __restrict__ beta,
    float* __restrict__ xout, float* __restrict__ hout)
{
    __shared__ float2 s_in[2][TNP][2 * H];
    __shared__ float2 s_h1[2][TNP][H];
    __shared__ float  s_h2[TN][H];
    __shared__ float  s_mu[TN], s_rs[TN];

    const int j = threadIdx.x;
    const int g = j >> 6;
    const int t = j & 63;
    const int c0 = t, c1 = t + 64;
    const int n0 = blockIdx.x * TN + g * GN;

    #pragma unroll
    for (int p = 0; p < TNP; p++) {
        int na = n0 + 2 * p, nb = na + 1;
        float ha0 = 0.f, ha1 = 0.f, hb0 = 0.f, hb1 = 0.f;
        float aa0 = 0.f, aa1 = 0.f, ab0 = 0.f, ab1 = 0.f;
        if (na < n) {
            float c = g_cnt[na]; c = c < 1.0f ? 1.0f : c; float ic = 1.0f / c;
            ha0 = h[(long)na * H + c0]; ha1 = h[(long)na * H + c1];
            aa0 = g_agg[(long)na * H + c0] * ic; aa1 = g_agg[(long)na * H + c1] * ic;
        }
        if (nb < n) {
            float c = g_cnt[nb]; c = c < 1.0f ? 1.0f : c; float ic = 1.0f / c;
            hb0 = h[(long)nb * H + c0]; hb1 = h[(long)nb * H + c1];
            ab0 = g_agg[(long)nb * H + c0] * ic; ab1 = g_agg[(long)nb * H + c1] * ic;
        }
        s_in[g][p][c0]     = make_float2(ha0, hb0);
        s_in[g][p][c1]     = make_float2(ha1, hb1);
        s_in[g][p][H + c0] = make_float2(aa0, ab0);
        s_in[g][p][H + c1] = make_float2(aa1, ab1);
    }
    __syncthreads();

    u64 acc0[TNP], acc1[TNP];

    // ---- Layer n1: 256 -> 128 ----
    {
        u64 ba = pack2(bn1[c0]), bb = pack2(bn1[c1]);
        #pragma unroll
        for (int p = 0; p < TNP; p++) { acc0[p] = ba; acc1[p] = bb; }
        #pragma unroll 2
        for (int kk = 0; kk < 64; kk++) {
            int k = kk * 4;
            u64 wa0 = pack2(Wn1[(k + 0) * H + c0]);
            u64 wa1 = pack2(Wn1[(k + 1) * H + c0]);
            u64 wa2 = pack2(Wn1[(k + 2) * H + c0]);
            u64 wa3 = pack2(Wn1[(k + 3) * H + c0]);
            u64 wb0 = pack2(Wn1[(k + 0) * H + c1]);
            u64 wb1 = pack2(Wn1[(k + 1) * H + c1]);
            u64 wb2 = pack2(Wn1[(k + 2) * H + c1]);
            u64 wb3 = pack2(Wn1[(k + 3) * H + c1]);
            #pragma unroll
            for (int p = 0; p < TNP; p++) {
                ulonglong2 A0 = *(const ulonglong2*)&s_in[g][p][k];
                ulonglong2 A1 = *(const ulonglong2*)&s_in[g][p][k + 2];
                ffma2(acc0[p], A0.x, wa0); ffma2(acc1[p], A0.x, wb0);
                ffma2(acc0[p], A0.y, wa1); ffma2(acc1[p], A0.y, wb1);
                ffma2(acc0[p], A1.x, wa2); ffma2(acc1[p], A1.x, wb2);
                ffma2(acc0[p], A1.y, wa3); ffma2(acc1[p], A1.y, wb3);
            }
        }
        #pragma unroll
        for (int p = 0; p < TNP; p++) {
            s_h1[g][p][c0] = silu2(acc0[p]);
            s_h1[g][p][c1] = silu2(acc1[p]);
        }
    }
    __syncthreads();

    // ---- Layer n2: 128 -> 128, residual ----
    {
        u64 ba = pack2(bn2[c0]), bb = pack2(bn2[c1]);
        #pragma unroll
        for (int p = 0; p < TNP; p++) { acc0[p] = ba; acc1[p] = bb; }
        #pragma unroll 2
        for (int kk = 0; kk < 32; kk++) {
            int k = kk * 4;
            u64 wa0 = pack2(Wn2[(k + 0) * H + c0]);
            u64 wa1 = pack2(Wn2[(k + 1) * H + c0]);
            u64 wa2 = pack2(Wn2[(k + 2) * H + c0]);
            u64 wa3 = pack2(Wn2[(k + 3) * H + c0]);
            u64 wb0 = pack2(Wn2[(k + 0) * H + c1]);
            u64 wb1 = pack2(Wn2[(k + 1) * H + c1]);
            u64 wb2 = pack2(Wn2[(k + 2) * H + c1]);
            u64 wb3 = pack2(Wn2[(k + 3) * H + c1]);
            #pragma unroll
            for (int p = 0; p < TNP; p++) {
                ulonglong2 A0 = *(const ulonglong2*)&s_h1[g][p][k];
                ulonglong2 A1 = *(const ulonglong2*)&s_h1[g][p][k + 2];
                ffma2(acc0[p], A0.x, wa0); ffma2(acc1[p], A0.x, wb0);
                ffma2(acc0[p], A0.y, wa1); ffma2(acc1[p], A0.y, wb1);
                ffma2(acc0[p], A1.x, wa2); ffma2(acc1[p], A1.x, wb2);
                ffma2(acc0[p], A1.y, wa3); ffma2(acc1[p], A1.y, wb3);
            }
        }
        #pragma unroll
        for (int p = 0; p < TNP; p++) {
            int na = n0 + 2 * p, nb = na + 1;
            float2 va = unpack2(acc0[p]);
            float2 vb = unpack2(acc1[p]);
            float ha0 = (na < n) ? h[(long)na * H + c0] : 0.0f;
            float ha1 = (na < n) ? h[(long)na * H + c1] : 0.0f;
            float hb0 = (nb < n) ? h[(long)nb * H + c0] : 0.0f;
            float hb1 = (nb < n) ? h[(long)nb * H + c1] : 0.0f;
            int la = g * GN + 2 * p, lb = la + 1;
            s_h2[la][c0] = ha0 + va.x;
            s_h2[la][c1] = ha1 + vb.x;
            s_h2[lb][c0] = hb0 + va.y;
            s_h2[lb][c1] = hb1 + vb.y;
        }
    }
    __syncthreads();

    // ---- LayerNorm stats ----
    {
        int wid = j >> 5, lane = j & 31;
        #pragma unroll
        for (int q = 0; q < 4; q++) {
            int e = wid * 4 + q;
            float v0 = s_h2[e][lane];
            float v1 = s_h2[e][lane + 32];
            float v2 = s_h2[e][lane + 64];
            float v3 = s_h2[e][lane + 96];
            float s  = v0 + v1 + v2 + v3;
            float ss = v0 * v0 + v1 * v1 + v2 * v2 + v3 * v3;
            #pragma unroll
            for (int off = 16; off > 0; off >>= 1) {
                s  += __shfl_down_sync(0xffffffffu, s, off);
                ss += __shfl_down_sync(0xffffffffu, ss, off);
            }
            if (lane == 0) {
                float mu = s * (1.0f / H);
                float var = ss * (1.0f / H) - mu * mu;
                s_mu[e] = mu;
                s_rs[e] = rsqrtf(var + 1e-5f);
            }
        }
    }
    __syncthreads();

    // ---- Normalize + SiLU + outputs ----
    const int nb0 = blockIdx.x * TN;
    float gj = gamma[j], bj = beta[j];
    #pragma unroll
    for (int e = 0; e < TN; e++) {
        int ng = nb0 + e;
        if (ng < n) {
            float v = (s_h2[e][j] - s_mu[e]) * s_rs[e] * gj + bj;
            hout[(long)ng * H + j] = silu(v);
            if (j < 3) {
                float c = g_cnt[ng]; c = c < 1.0f ? 1.0f : c;
                xout[ng * 3 + j] = x[ng * 3 + j] + g_dx[ng * 3 + j] / c;
            }
        }
    }
}

extern "C" void kernel_launch(void* const* d_in, const int* in_sizes, int n_in,
                              void* d_out, int out_size)
{
    const float* x    = (const float*)d_in[0];
    const float* h    = (const float*)d_in[1];
    const int*   ei   = (const int*)d_in[2];
    const float* We1  = (const float*)d_in[3];
    const float* be1  = (const float*)d_in[4];
    const float* We2  = (const float*)d_in[5];
    const float* be2  = (const float*)d_in[6];
    const float* Wc1  = (const float*)d_in[7];
    const float* bc1  = (const float*)d_in[8];
    const float* Wc2  = (const float*)d_in[9];
    const float* bc2  = (const float*)d_in[10];
    const float* Wn1  = (const float*)d_in[11];
    const float* bn1  = (const float*)d_in[12];
    const float* Wn2  = (const float*)d_in[13];
    const float* bn2  = (const float*)d_in[14];
    const float* gamma = (const float*)d_in[15];
    const float* beta  = (const float*)d_in[16];

    int n = in_sizes[0] / 3;       // 50000
    int E = in_sizes[2] / 2;       // 800000

    float* xout = (float*)d_out;              // [n,3]
    float* hout = xout + (size_t)n * 3;       // [n,128]

    zero_kernel<<<256, 256>>>(n);
    prep_kernel<<<32, 512>>>(We2, Wc1);
    pq_kernel<<<(n + TN - 1) / TN, 128>>>(h, We1, n);
    edge_kernel<<<(E + TEK - 1) / TEK, 128>>>(x, ei, E,
                                              We1, be1, be2, bc1, Wc2, bc2);
    node_kernel<<<(n + TN - 1) / TN, 128>>>(x, h, n, Wn1, bn1, Wn2, bn2,
                                            gamma, beta, xout, hout);
}

// round 10
// speedup vs baseline: 1.2489x; 1.2489x over previous
#include <cuda_runtime.h>

#define H 128
#define NMAX 50000
#define TEK 32          // edges per block (edge kernel)

// Scratch (no dynamic allocation allowed)
__device__ float g_agg[NMAX * H];
__device__ float g_dx[NMAX * 3];
__device__ float g_cnt[NMAX];
__device__ float g_P[NMAX * H];        // h @ We1[0:128]
__device__ float g_Q[NMAX * H];        // h @ We1[128:256]
__device__ float g_W2e[16 * 1024];     // We2 fragment-swizzled tf32 (S=16)
__device__ float g_W2c[16 * 1024];     // Wc1
__device__ float g_W1p[16 * 1024];     // We1[0:128]
__device__ float g_W1q[16 * 1024];     // We1[128:256]
__device__ float g_Wn2[16 * 1024];     // Wn2
__device__ float g_Wn1[32 * 1024];     // Wn1 (S=32, K=256)

__device__ __forceinline__ float silu(float v) {
    return v / (1.0f + __expf(-v));
}
__device__ __forceinline__ unsigned tf32u(float f) {
    unsigned r; asm("cvt.rna.tf32.f32 %0, %1;" : "=r"(r) : "f"(f));
    return r;
}
__device__ __forceinline__ float tf32f(float f) {
    return __uint_as_float(tf32u(f));
}
__device__ __forceinline__ void mma_tf32(float c[4],
    unsigned a0, unsigned a1, unsigned a2, unsigned a3,
    unsigned b0, unsigned b1)
{
    asm("mma.sync.aligned.m16n8k8.row.col.f32.tf32.tf32.f32 "
        "{%0,%1,%2,%3},{%4,%5,%6,%7},{%8,%9},{%0,%1,%2,%3};"
        : "+f"(c[0]), "+f"(c[1]), "+f"(c[2]), "+f"(c[3])
        : "r"(a0), "r"(a1), "r"(a2), "r"(a3), "r"(b0), "r"(b1));
}
__device__ __forceinline__ void ldsm4(unsigned &r0, unsigned &r1,
                                      unsigned &r2, unsigned &r3,
                                      unsigned addr)
{
    asm volatile("ldmatrix.sync.aligned.m8n8.x4.shared.b16 {%0,%1,%2,%3}, [%4];"
        : "=r"(r0), "=r"(r1), "=r"(r2), "=r"(r3) : "r"(addr));
}

__global__ void zero_kernel(int n) {
    int total = n * H + n * 3 + n;
    for (int i = blockIdx.x * blockDim.x + threadIdx.x; i < total;
         i += gridDim.x * blockDim.x) {
        if (i < n * H) g_agg[i] = 0.0f;
        else if (i < n * H + n * 3) g_dx[i - n * H] = 0.0f;
        else g_cnt[i - n * H - n * 3] = 0.0f;
    }
}

// Fragment-swizzle weights into tf32 B-frag order:
// dst[((tp*S+s)*32+lane)*2 + r] = tf32(W[8s + tg + 4r][8tp + g])
__device__ __forceinline__ void swz_store(float* dst, const float* W,
                                          int S, int idx)
{
    int r = idx & 1;
    int lane = (idx >> 1) & 31;
    int sp = idx >> 6;             // tp*S + s
    int s = sp % S, tp = sp / S;
    int g = lane >> 2, tg = lane & 3;
    dst[idx] = tf32f(W[(8 * s + tg + 4 * r) * H + 8 * tp + g]);
}

__global__ void prep_kernel(const float* __restrict__ We2,
                            const float* __restrict__ Wc1,
                            const float* __restrict__ Wn1,
                            const float* __restrict__ Wn2,
                            const float* __restrict__ We1)
{
    int i = blockIdx.x * blockDim.x + threadIdx.x;
    if (i < 16384)       swz_store(g_W2e, We2, 16, i);
    else if (i < 32768)  swz_store(g_W2c, Wc1, 16, i - 16384);
    else if (i < 49152)  swz_store(g_W1p, We1, 16, i - 32768);
    else if (i < 65536)  swz_store(g_W1q, We1 + 128 * H, 16, i - 49152);
    else if (i < 81920)  swz_store(g_Wn2, Wn2, 16, i - 65536);
    else if (i < 114688) swz_store(g_Wn1, Wn1, 32, i - 81920);
}

// ---------------------------------------------------------------------------
// PQ via tf32 MMA: 32 nodes/block, warps split N (32 cols each).
// P = h @ We1[0:128,:], Q = h @ We1[128:256,:], outputs fp32.
// ---------------------------------------------------------------------------
__global__ __launch_bounds__(128) void pq_kernel(
    const float* __restrict__ h, int n)
{
    __shared__ float s_tf[32][132];

    const int j = threadIdx.x;
    const int w = j >> 5, lane = j & 31;
    const int g = lane >> 2, tg = lane & 3;
    const int n0 = blockIdx.x * 32;

    const int rowA = lane & 15;
    const int colA = (lane & 16) ? 4 : 0;
    const unsigned baseA0 = (unsigned)__cvta_generic_to_shared(&s_tf[rowA][colA]);
    const unsigned baseA1 = (unsigned)__cvta_generic_to_shared(&s_tf[16 + rowA][colA]);

    #pragma unroll 4
    for (int e = 0; e < 32; e++) {
        int nd = n0 + e;
        s_tf[e][j] = (nd < n) ? tf32f(h[(long)nd * H + j]) : 0.f;
    }
    __syncthreads();

    float cc[4][2][4];

    // ---- P ----
    #pragma unroll
    for (int t = 0; t < 4; t++)
        #pragma unroll
        for (int mt = 0; mt < 2; mt++)
            #pragma unroll
            for (int q = 0; q < 4; q++) cc[t][mt][q] = 0.f;

    #pragma unroll 4
    for (int s = 0; s < 16; s++) {
        unsigned a00, a01, a02, a03, a10, a11, a12, a13;
        ldsm4(a00, a01, a02, a03, baseA0 + 32u * s);
        ldsm4(a10, a11, a12, a13, baseA1 + 32u * s);
        #pragma unroll
        for (int t = 0; t < 4; t++) {
            float2 bv = *(const float2*)&g_W1p[(((4 * w + t) * 16 + s) * 32 + lane) * 2];
            unsigned b0 = __float_as_uint(bv.x), b1 = __float_as_uint(bv.y);
            mma_tf32(cc[t][0], a00, a01, a02, a03, b0, b1);
            mma_tf32(cc[t][1], a10, a11, a12, a13, b0, b1);
        }
    }
    #pragma unroll
    for (int t = 0; t < 4; t++) {
        int col = 32 * w + 8 * t + 2 * tg;
        #pragma unroll
        for (int mt = 0; mt < 2; mt++) {
            int nd0 = n0 + g + 16 * mt, nd1 = nd0 + 8;
            if (nd0 < n) *(float2*)&g_P[(long)nd0 * H + col] =
                make_float2(cc[t][mt][0], cc[t][mt][1]);
            if (nd1 < n) *(float2*)&g_P[(long)nd1 * H + col] =
                make_float2(cc[t][mt][2], cc[t][mt][3]);
        }
    }

    // ---- Q ---- (s_tf unchanged, read-only; no barrier needed)
    #pragma unroll
    for (int t = 0; t < 4; t++)
        #pragma unroll
        for (int mt = 0; mt < 2; mt++)
            #pragma unroll
            for (int q = 0; q < 4; q++) cc[t][mt][q] = 0.f;

    #pragma unroll 4
    for (int s = 0; s < 16; s++) {
        unsigned a00, a01, a02, a03, a10, a11, a12, a13;
        ldsm4(a00, a01, a02, a03, baseA0 + 32u * s);
        ldsm4(a10, a11, a12, a13, baseA1 + 32u * s);
        #pragma unroll
        for (int t = 0; t < 4; t++) {
            float2 bv = *(const float2*)&g_W1q[(((4 * w + t) * 16 + s) * 32 + lane) * 2];
            unsigned b0 = __float_as_uint(bv.x), b1 = __float_as_uint(bv.y);
            mma_tf32(cc[t][0], a00, a01, a02, a03, b0, b1);
            mma_tf32(cc[t][1], a10, a11, a12, a13, b0, b1);
        }
    }
    #pragma unroll
    for (int t = 0; t < 4; t++) {
        int col = 32 * w + 8 * t + 2 * tg;
        #pragma unroll
        for (int mt = 0; mt < 2; mt++) {
            int nd0 = n0 + g + 16 * mt, nd1 = nd0 + 8;
            if (nd0 < n) *(float2*)&g_Q[(long)nd0 * H + col] =
                make_float2(cc[t][mt][0], cc[t][mt][1]);
            if (nd1 < n) *(float2*)&g_Q[(long)nd1 * H + col] =
                make_float2(cc[t][mt][2], cc[t][mt][3]);
        }
    }
}

// ---------------------------------------------------------------------------
// Edge kernel: R8 structure (TEK=32, warps split N, ldmatrix A, single
// tf32 smem buffer recycled f1 -> f2; agg scatter uses tf32-rounded f2).
// ---------------------------------------------------------------------------
__global__ __launch_bounds__(128) void edge_kernel(
    const float* __restrict__ x, const int* __restrict__ ei, int E,
    const float* __restrict__ We1, const float* __restrict__ be1,
    const float* __restrict__ be2, const float* __restrict__ bc1,
    const float* __restrict__ Wc2, const float* __restrict__ bc2)
{
    __shared__ float s_tf[TEK][132];
    __shared__ float s_rel[TEK][3];
    __shared__ float s_d2[TEK];
    __shared__ int   s_row[TEK], s_col[TEK];
    __shared__ float s_gp[4][TEK];
    __shared__ float s_gate[TEK];

    const int j = threadIdx.x;
    const int w = j >> 5, lane = j & 31;
    const int g = lane >> 2, tg = lane & 3;
    const long e0 = (long)blockIdx.x * TEK;

    const int rowA = lane & 15;
    const int colA = (lane & 16) ? 4 : 0;
    const unsigned baseA0 =
        (unsigned)__cvta_generic_to_shared(&s_tf[rowA][colA]);
    const unsigned baseA1 =
        (unsigned)__cvta_generic_to_shared(&s_tf[16 + rowA][colA]);

    // Phase 0: per-edge scalars
    if (j < TEK) {
        long e = e0 + j;
        int r = -1, c = 0;
        float rx = 0.f, ry = 0.f, rz = 0.f, d2 = 0.f;
        if (e < E) {
            r = ei[e]; c = ei[E + e];
            rx = x[r * 3 + 0] - x[c * 3 + 0];
            ry = x[r * 3 + 1] - x[c * 3 + 1];
            rz = x[r * 3 + 2] - x[c * 3 + 2];
            d2 = rx * rx + ry * ry + rz * rz;
        }
        s_row[j] = r; s_col[j] = c; s_d2[j] = d2;
        s_rel[j][0] = rx; s_rel[j][1] = ry; s_rel[j][2] = rz;
    }
    __syncthreads();

    // Phase 1: layer-1 elementwise (thread j = column j), stored tf32
    {
        float wl = We1[256 * H + j];
        float b  = be1[j];
        #pragma unroll 4
        for (int e = 0; e < TEK; e++) {
            int r = s_row[e], c = s_col[e];
            float v = 0.f;
            if (r >= 0)
                v = silu(g_P[(long)r * H + j] + g_Q[(long)c * H + j]
                         + s_d2[e] * wl + b);
            s_tf[e][j] = tf32f(v);
        }
    }
    __syncthreads();

    float cc[4][2][4];

    // ---- GEMM1: f2 = silu(f1 @ We2 + be2) ----
    #pragma unroll
    for (int t = 0; t < 4; t++)
        #pragma unroll
        for (int mt = 0; mt < 2; mt++)
            #pragma unroll
            for (int q = 0; q < 4; q++) cc[t][mt][q] = 0.f;

    #pragma unroll 4
    for (int s = 0; s < 16; s++) {
        unsigned a00, a01, a02, a03, a10, a11, a12, a13;
        ldsm4(a00, a01, a02, a03, baseA0 + 32u * s);
        ldsm4(a10, a11, a12, a13, baseA1 + 32u * s);
        #pragma unroll
        for (int t = 0; t < 4; t++) {
            float2 bv = *(const float2*)&g_W2e[(((4 * w + t) * 16 + s) * 32 + lane) * 2];
            unsigned b0 = __float_as_uint(bv.x), b1 = __float_as_uint(bv.y);
            mma_tf32(cc[t][0], a00, a01, a02, a03, b0, b1);
            mma_tf32(cc[t][1], a10, a11, a12, a13, b0, b1);
        }
    }
    __syncthreads();   // all warps done reading s_tf (f1)

    // epilogue: silu + bias -> tf32 into s_tf
    #pragma unroll
    for (int t = 0; t < 4; t++) {
        int col = 32 * w + 8 * t + 2 * tg;
        float b0 = be2[col], b1 = be2[col + 1];
        #pragma unroll
        for (int mt = 0; mt < 2; mt++) {
            int r0 = g + 16 * mt, r1 = r0 + 8;
            s_tf[r0][col]     = tf32f(silu(cc[t][mt][0] + b0));
            s_tf[r0][col + 1] = tf32f(silu(cc[t][mt][1] + b1));
            s_tf[r1][col]     = tf32f(silu(cc[t][mt][2] + b0));
            s_tf[r1][col + 1] = tf32f(silu(cc[t][mt][3] + b1));
        }
    }
    __syncthreads();

    // agg scatter (coalesced: thread j = column j), tf32-rounded f2
    #pragma unroll 4
    for (int e = 0; e < TEK; e++) {
        int r = s_row[e];
        if (r >= 0) atomicAdd(&g_agg[(long)r * H + j], s_tf[e][j]);
    }

    // ---- GEMM2: gate hidden = silu(f2 @ Wc1 + bc1), consumed in registers ----
    #pragma unroll
    for (int t = 0; t < 4; t++)
        #pragma unroll
        for (int mt = 0; mt < 2; mt++)
            #pragma unroll
            for (int q = 0; q < 4; q++) cc[t][mt][q] = 0.f;

    #pragma unroll 4
    for (int s = 0; s < 16; s++) {
        unsigned a00, a01, a02, a03, a10, a11, a12, a13;
        ldsm4(a00, a01, a02, a03, baseA0 + 32u * s);
        ldsm4(a10, a11, a12, a13, baseA1 + 32u * s);
        #pragma unroll
        for (int t = 0; t < 4; t++) {
            float2 bv = *(const float2*)&g_W2c[(((4 * w + t) * 16 + s) * 32 + lane) * 2];
            unsigned b0 = __float_as_uint(bv.x), b1 = __float_as_uint(bv.y);
            mma_tf32(cc[t][0], a00, a01, a02, a03, b0, b1);
            mma_tf32(cc[t][1], a10, a11, a12, a13, b0, b1);
        }
    }

    // gate partial dot with Wc2; thread covers edge rows g, g+8, g+16, g+24
    {
        float p0 = 0.f, p1 = 0.f, p2 = 0.f, p3 = 0.f;
        #pragma unroll
        for (int t = 0; t < 4; t++) {
            int col = 32 * w + 8 * t + 2 * tg;
            float w0 = Wc2[col], w1 = Wc2[col + 1];
            float b0 = bc1[col], b1 = bc1[col + 1];
            p0 += silu(cc[t][0][0] + b0) * w0 + silu(cc[t][0][1] + b1) * w1;
            p1 += silu(cc[t][0][2] + b0) * w0 + silu(cc[t][0][3] + b1) * w1;
            p2 += silu(cc[t][1][0] + b0) * w0 + silu(cc[t][1][1] + b1) * w1;
            p3 += silu(cc[t][1][2] + b0) * w0 + silu(cc[t][1][3] + b1) * w1;
        }
        p0 += __shfl_xor_sync(0xffffffffu, p0, 1);
        p0 += __shfl_xor_sync(0xffffffffu, p0, 2);
        p1 += __shfl_xor_sync(0xffffffffu, p1, 1);
        p1 += __shfl_xor_sync(0xffffffffu, p1, 2);
        p2 += __shfl_xor_sync(0xffffffffu, p2, 1);
        p2 += __shfl_xor_sync(0xffffffffu, p2, 2);
        p3 += __shfl_xor_sync(0xffffffffu, p3, 1);
        p3 += __shfl_xor_sync(0xffffffffu, p3, 2);
        if (tg == 0) {
            s_gp[w][g]      = p0;
            s_gp[w][g + 8]  = p1;
            s_gp[w][g + 16] = p2;
            s_gp[w][g + 24] = p3;
        }
    }
    __syncthreads();

    if (j < TEK)
        s_gate[j] = s_gp[0][j] + s_gp[1][j] + s_gp[2][j] + s_gp[3][j] + bc2[0];
    __syncthreads();

    {
        int e = j >> 2, c = j & 3;    // 128 threads = 32 edges x 4
        int r = s_row[e];
        if (r >= 0) {
            if (c < 3) atomicAdd(&g_dx[r * 3 + c], s_rel[e][c] * s_gate[e]);
            else       atomicAdd(&g_cnt[r], 1.0f);
        }
    }
}

// ---------------------------------------------------------------------------
// Node kernel via tf32 MMA: 32 nodes/block, warps split N.
// nin = [h, agg/cnt] (K=256) -> n1 (silu) -> dh (K=128) -> residual+LN+silu.
// ---------------------------------------------------------------------------
__global__ __launch_bounds__(128) void node_kernel(
    const float* __restrict__ x, const float* __restrict__ h, int n,
    const float* __restrict__ bn1, const float* __restrict__ bn2,
    const float* __restrict__ gamma, const float* __restrict__ beta,
    float* __restrict__ xout, float* __restrict__ hout)
{
    __shared__ float s_tf[32][260];    // cols 0..255 = A operand; recycled
    __shared__ float s_mu[32], s_rs[32];

    const int j = threadIdx.x;
    const int w = j >> 5, lane = j & 31;
    const int g = lane >> 2, tg = lane & 3;
    const int n0 = blockIdx.x * 32;

    const int rowA = lane & 15;
    const int colA = (lane & 16) ? 4 : 0;
    const unsigned baseA0 = (unsigned)__cvta_generic_to_shared(&s_tf[rowA][colA]);
    const unsigned baseA1 = (unsigned)__cvta_generic_to_shared(&s_tf[16 + rowA][colA]);

    // Phase A: thread j loads col j of h and agg/cnt for 32 nodes (tf32)
    #pragma unroll 4
    for (int e = 0; e < 32; e++) {
        int nd = n0 + e;
        float hv = 0.f, av = 0.f;
        if (nd < n) {
            float c = g_cnt[nd]; c = c < 1.0f ? 1.0f : c;
            hv = h[(long)nd * H + j];
            av = g_agg[(long)nd * H + j] / c;
        }
        s_tf[e][j]     = tf32f(hv);
        s_tf[e][H + j] = tf32f(av);
    }
    __syncthreads();

    float cc[4][2][4];

    // ---- GEMM1: n1 = silu(nin @ Wn1 + bn1), K=256 (32 steps) ----
    #pragma unroll
    for (int t = 0; t < 4; t++)
        #pragma unroll
        for (int mt = 0; mt < 2; mt++)
            #pragma unroll
            for (int q = 0; q < 4; q++) cc[t][mt][q] = 0.f;

    #pragma unroll 4
    for (int s = 0; s < 32; s++) {
        unsigned a00, a01, a02, a03, a10, a11, a12, a13;
        ldsm4(a00, a01, a02, a03, baseA0 + 32u * s);
        ldsm4(a10, a11, a12, a13, baseA1 + 32u * s);
        #pragma unroll
        for (int t = 0; t < 4; t++) {
            float2 bv = *(const float2*)&g_Wn1[(((4 * w + t) * 32 + s) * 32 + lane) * 2];
            unsigned b0 = __float_as_uint(bv.x), b1 = __float_as_uint(bv.y);
            mma_tf32(cc[t][0], a00, a01, a02, a03, b0, b1);
            mma_tf32(cc[t][1], a10, a11, a12, a13, b0, b1);
        }
    }
    __syncthreads();   // all warps done reading nin

    // epilogue: silu+bias -> tf32 into s_tf cols 0..127 (A of GEMM2)
    #pragma unroll
    for (int t = 0; t < 4; t++) {
        int col = 32 * w + 8 * t + 2 * tg;
        float b0 = bn1[col], b1 = bn1[col + 1];
        #pragma unroll
        for (int mt = 0; mt < 2; mt++) {
            int r0 = g + 16 * mt, r1 = r0 + 8;
            s_tf[r0][col]     = tf32f(silu(cc[t][mt][0] + b0));
            s_tf[r0][col + 1] = tf32f(silu(cc[t][mt][1] + b1));
            s_tf[r1][col]     = tf32f(silu(cc[t][mt][2] + b0));
            s_tf[r1][col + 1] = tf32f(silu(cc[t][mt][3] + b1));
        }
    }
    __syncthreads();

    // ---- GEMM2: dh = n1 @ Wn2 + bn2, K=128 (16 steps) ----
    #pragma unroll
    for (int t = 0; t < 4; t++)
        #pragma unroll
        for (int mt = 0; mt < 2; mt++)
            #pragma unroll
            for (int q = 0; q < 4; q++) cc[t][mt][q] = 0.f;

    #pragma unroll 4
    for (int s = 0; s < 16; s++) {
        unsigned a00, a01, a02, a03, a10, a11, a12, a13;
        ldsm4(a00, a01, a02, a03, baseA0 + 32u * s);
        ldsm4(a10, a11, a12, a13, baseA1 + 32u * s);
        #pragma unroll
        for (int t = 0; t < 4; t++) {
            float2 bv = *(const float2*)&g_Wn2[(((4 * w + t) * 16 + s) * 32 + lane) * 2];
            unsigned b0 = __float_as_uint(bv.x), b1 = __float_as_uint(bv.y);
            mma_tf32(cc[t][0], a00, a01, a02, a03, b0, b1);
            mma_tf32(cc[t][1], a10, a11, a12, a13, b0, b1);
        }
    }

    // epilogue: h2 = h + dh (exact fp32) -> s_tf cols 128..255 (free region)
    #pragma unroll
    for (int t = 0; t < 4; t++) {
        int col = 32 * w + 8 * t + 2 * tg;
        float b0 = bn2[col], b1 = bn2[col + 1];
        #pragma unroll
        for (int mt = 0; mt < 2; mt++) {
            int r0 = g + 16 * mt, r1 = r0 + 8;
            int nd0 = n0 + r0, nd1 = n0 + r1;
            float h00 = (nd0 < n) ? h[(long)nd0 * H + col]     : 0.f;
            float h01 = (nd0 < n) ? h[(long)nd0 * H + col + 1] : 0.f;
            float h10 = (nd1 < n) ? h[(long)nd1 * H + col]     : 0.f;
            float h11 = (nd1 < n) ? h[(long)nd1 * H + col + 1] : 0.f;
            s_tf[r0][H + col]     = h00 + cc[t][mt][0] + b0;
            s_tf[r0][H + col + 1] = h01 + cc[t][mt][1] + b1;
            s_tf[r1][H + col]     = h10 + cc[t][mt][2] + b0;
            s_tf[r1][H + col + 1] = h11 + cc[t][mt][3] + b1;
        }
    }
    __syncthreads();

    // ---- LayerNorm stats: 4 warps x 8 nodes ----
    #pragma unroll
    for (int q = 0; q < 8; q++) {
        int e = w * 8 + q;
        float v0 = s_tf[e][H + lane];
        float v1 = s_tf[e][H + lane + 32];
        float v2 = s_tf[e][H + lane + 64];
        float v3 = s_tf[e][H + lane + 96];
        float s  = v0 + v1 + v2 + v3;
        float ss = v0 * v0 + v1 * v1 + v2 * v2 + v3 * v3;
        #pragma unroll
        for (int off = 16; off > 0; off >>= 1) {
            s  += __shfl_down_sync(0xffffffffu, s, off);
            ss += __shfl_down_sync(0xffffffffu, ss, off);
        }
        if (lane == 0) {
            float mu = s * (1.0f / H);
            float var = ss * (1.0f / H) - mu * mu;
            s_mu[e] = mu;
            s_rs[e] = rsqrtf(var + 1e-5f);
        }
    }
    __syncthreads();

    // ---- Normalize + SiLU + outputs ----
    float gj = gamma[j], bj = beta[j];
    #pragma unroll 4
    for (int e = 0; e < 32; e++) {
        int nd = n0 + e;
        if (nd < n) {
            float v = (s_tf[e][H + j] - s_mu[e]) * s_rs[e] * gj + bj;
            hout[(long)nd * H + j] = silu(v);
            if (j < 3) {
                float c = g_cnt[nd]; c = c < 1.0f ? 1.0f : c;
                xout[nd * 3 + j] = x[nd * 3 + j] + g_dx[nd * 3 + j] / c;
            }
        }
    }
}

extern "C" void kernel_launch(void* const* d_in, const int* in_sizes, int n_in,
                              void* d_out, int out_size)
{
    const float* x    = (const float*)d_in[0];
    const float* h    = (const float*)d_in[1];
    const int*   ei   = (const int*)d_in[2];
    const float* We1  = (const float*)d_in[3];
    const float* be1  = (const float*)d_in[4];
    const float* We2  = (const float*)d_in[5];
    const float* be2  = (const float*)d_in[6];
    const float* Wc1  = (const float*)d_in[7];
    const float* bc1  = (const float*)d_in[8];
    const float* Wc2  = (const float*)d_in[9];
    const float* bc2  = (const float*)d_in[10];
    const float* Wn1  = (const float*)d_in[11];
    const float* bn1  = (const float*)d_in[12];
    const float* Wn2  = (const float*)d_in[13];
    const float* bn2  = (const float*)d_in[14];
    const float* gamma = (const float*)d_in[15];
    const float* beta  = (const float*)d_in[16];

    int n = in_sizes[0] / 3;       // 50000
    int E = in_sizes[2] / 2;       // 800000

    float* xout = (float*)d_out;              // [n,3]
    float* hout = xout + (size_t)n * 3;       // [n,128]

    zero_kernel<<<256, 256>>>(n);
    prep_kernel<<<448, 256>>>(We2, Wc1, Wn1, Wn2, We1);
    pq_kernel<<<(n + 31) / 32, 128>>>(h, n);
    edge_kernel<<<(E + TEK - 1) / TEK, 128>>>(x, ei, E,
                                              We1, be1, be2, bc1, Wc2, bc2);
    node_kernel<<<(n + 31) / 32, 128>>>(x, h, n, bn1, bn2,
                                        gamma, beta, xout, hout);
}